// round 4
// baseline (speedup 1.0000x reference)
#include <cuda_runtime.h>

// Problem constants
#define BSZ 4
#define CIN_ 256
#define CQK_ 128
#define NPT 4096   // H*W*D = 16*16*16

// Scratch for projections (device globals: no allocation allowed)
__device__ float g_q[BSZ * NPT * CQK_];   // [b][n][o]   8 MB
__device__ float g_k[BSZ * NPT * CQK_];   // [b][m][o]   8 MB
__device__ float g_v[BSZ * NPT * CIN_];   // [b][m][c]  16 MB

// ---------------- f32x2 packed-math helpers (sm_100+) ----------------
typedef unsigned long long u64;

__device__ __forceinline__ u64 pack2(float lo, float hi) {
    u64 r; asm("mov.b64 %0, {%1, %2};" : "=l"(r) : "f"(lo), "f"(hi)); return r;
}
__device__ __forceinline__ void unpack2(u64 v, float& lo, float& hi) {
    asm("mov.b64 {%0, %1}, %2;" : "=f"(lo), "=f"(hi) : "l"(v));
}
__device__ __forceinline__ void ffma2(u64& d, u64 a, u64 b) {
    asm("fma.rn.f32x2 %0, %1, %2, %0;" : "+l"(d) : "l"(a), "l"(b));
}
__device__ __forceinline__ void fmul2(u64& d, u64 a) {
    asm("mul.rn.f32x2 %0, %0, %1;" : "+l"(d) : "l"(a));
}

// ---------------- Projection GEMM ----------------
// out[b][n][o] = sum_c W[o][c] * X[b][c][n] + bias[o]
// Tile: 64n x 64o, K-chunks of 32. Threads 256 = 16(tn) x 16(to), 4x4 micro-tile.
template<int OUT, int DST>
__global__ __launch_bounds__(256)
void proj_kernel(const float* __restrict__ W, const float* __restrict__ bias,
                 const float* __restrict__ X)
{
    __shared__ float sX[32 * 64];   // [c][n]
    __shared__ float sW[32 * 68];   // [c][o] stride 68 (pad)

    float* out = (DST == 0) ? g_q : (DST == 1) ? g_k : g_v;

    const int tid = threadIdx.x;
    const int tn = tid >> 4, to = tid & 15;
    const int b  = blockIdx.z;
    const int n0 = blockIdx.x * 64;
    const int o0 = blockIdx.y * 64;
    const float* Xb = X + (size_t)b * CIN_ * NPT;

    u64 acc[4][2];
#pragma unroll
    for (int i = 0; i < 4; i++) { acc[i][0] = 0ull; acc[i][1] = 0ull; }

    for (int ct = 0; ct < CIN_; ct += 32) {
        // load X tile: coalesced copy (rows c, contiguous n)
#pragma unroll
        for (int r = 0; r < 8; r++) {
            int idx = tid + r * 256;
            int c = idx >> 6, n = idx & 63;
            sX[c * 64 + n] = Xb[(size_t)(ct + c) * NPT + n0 + n];
        }
        // load W tile transposed: read coalesced in c, write [c][o]
#pragma unroll
        for (int r = 0; r < 8; r++) {
            int idx = tid + r * 256;
            int o = idx >> 5, c = idx & 31;
            sW[c * 68 + o] = W[(size_t)(o0 + o) * CIN_ + ct + c];
        }
        __syncthreads();

#pragma unroll 8
        for (int c = 0; c < 32; c++) {
            float4 xf = *(const float4*)&sX[c * 64 + 4 * tn];
            ulonglong2 wf = *(const ulonglong2*)&sW[c * 68 + 4 * to];
            u64 x0 = pack2(xf.x, xf.x), x1 = pack2(xf.y, xf.y);
            u64 x2 = pack2(xf.z, xf.z), x3 = pack2(xf.w, xf.w);
            ffma2(acc[0][0], x0, wf.x); ffma2(acc[0][1], x0, wf.y);
            ffma2(acc[1][0], x1, wf.x); ffma2(acc[1][1], x1, wf.y);
            ffma2(acc[2][0], x2, wf.x); ffma2(acc[2][1], x2, wf.y);
            ffma2(acc[3][0], x3, wf.x); ffma2(acc[3][1], x3, wf.y);
        }
        __syncthreads();
    }

    float4 bv4 = *(const float4*)&bias[o0 + 4 * to];
    float* outb = out + (size_t)b * NPT * OUT;
#pragma unroll
    for (int i = 0; i < 4; i++) {
        float a0, a1, a2, a3;
        unpack2(acc[i][0], a0, a1); unpack2(acc[i][1], a2, a3);
        float4 r = make_float4(a0 + bv4.x, a1 + bv4.y, a2 + bv4.z, a3 + bv4.w);
        *(float4*)&outb[(size_t)(n0 + 4 * tn + i) * OUT + o0 + 4 * to] = r;
    }
}

// ---------------- Fused attention ----------------
// Per CTA: one batch b, 64 queries [n0, n0+64). Loop over 64-key tiles:
//   S = Q K^T (64x64, d=128), online softmax, O += P V (d_v=256).
// Thread map (256 thr): ty=tid/16 (4 query rows 4*ty..), tx=tid%16.
//   S phase: cols 4*tx..  PV phase: channels {2*tx + 32*g, +1} for g=0..7.
#define TSTR 68   // transposed smem stride (pad: 16B-aligned float4, conflict-free)

extern __shared__ __align__(16) float smem_attn[];

__global__ __launch_bounds__(256, 1)
void attn_kernel(const float* __restrict__ gin,
                 const float* __restrict__ gamma_p,
                 float* __restrict__ out)
{
    float* sQT = smem_attn;               // [128][68] (kk-major)
    float* sKT = sQT + 128 * TSTR;        // [128][68]
    float* sV  = sKT + 128 * TSTR;        // [64][256]
    float* sP  = sV + 64 * 256;           // [64][68]

    const int tid = threadIdx.x;
    const int ty = tid >> 4, tx = tid & 15;
    const int b  = blockIdx.y;
    const int n0 = blockIdx.x * 64;

    const float* qb = g_q + ((size_t)b * NPT + n0) * CQK_;
    const float* kb = g_k + (size_t)b * NPT * CQK_;
    const float* vb = g_v + (size_t)b * NPT * CIN_;

    // Load Q transposed: sQT[o][n]
#pragma unroll
    for (int r = 0; r < 32; r++) {
        int idx = tid + r * 256;
        int n = idx >> 7, o = idx & 127;
        sQT[o * TSTR + n] = qb[n * CQK_ + o];
    }

    u64 o2[4][8];
#pragma unroll
    for (int i = 0; i < 4; i++)
#pragma unroll
        for (int g = 0; g < 8; g++) o2[i][g] = 0ull;

    float mrun[4], lrun[4];
#pragma unroll
    for (int i = 0; i < 4; i++) { mrun[i] = -1e30f; lrun[i] = 0.0f; }

    for (int m0 = 0; m0 < NPT; m0 += 64) {
        __syncthreads();   // previous tile's sKT/sV/sP consumers done
        // K tile transposed: sKT[o][m]
#pragma unroll
        for (int r = 0; r < 32; r++) {
            int idx = tid + r * 256;
            int m = idx >> 7, o = idx & 127;
            sKT[o * TSTR + m] = kb[(size_t)(m0 + m) * CQK_ + o];
        }
        // V tile: direct vectorized copy, sV[m][c]
        {
            const float4* vsrc = (const float4*)(vb + (size_t)m0 * CIN_);
            float4* vdst = (float4*)sV;
#pragma unroll
            for (int r = 0; r < 16; r++) vdst[tid + r * 256] = vsrc[tid + r * 256];
        }
        __syncthreads();

        // ---- S = Q K^T (4x4 per thread, f32x2 pairs along key dim) ----
        u64 s2[4][2];
#pragma unroll
        for (int i = 0; i < 4; i++) { s2[i][0] = 0ull; s2[i][1] = 0ull; }
#pragma unroll 4
        for (int kk = 0; kk < 128; kk++) {
            float4 qf = *(const float4*)&sQT[kk * TSTR + 4 * ty];
            ulonglong2 kf = *(const ulonglong2*)&sKT[kk * TSTR + 4 * tx];
            u64 q0 = pack2(qf.x, qf.x), q1 = pack2(qf.y, qf.y);
            u64 q2 = pack2(qf.z, qf.z), q3 = pack2(qf.w, qf.w);
            ffma2(s2[0][0], q0, kf.x); ffma2(s2[0][1], q0, kf.y);
            ffma2(s2[1][0], q1, kf.x); ffma2(s2[1][1], q1, kf.y);
            ffma2(s2[2][0], q2, kf.x); ffma2(s2[2][1], q2, kf.y);
            ffma2(s2[3][0], q3, kf.x); ffma2(s2[3][1], q3, kf.y);
        }

        // ---- online softmax (row reductions over 16 tx lanes) ----
#pragma unroll
        for (int i = 0; i < 4; i++) {
            float v0, v1, v2v, v3;
            unpack2(s2[i][0], v0, v1); unpack2(s2[i][1], v2v, v3);
            float mx = fmaxf(fmaxf(v0, v1), fmaxf(v2v, v3));
#pragma unroll
            for (int off = 8; off; off >>= 1)
                mx = fmaxf(mx, __shfl_xor_sync(0xffffffffu, mx, off));
            float mnew = fmaxf(mrun[i], mx);
            float f = __expf(mrun[i] - mnew);
            float p0 = __expf(v0 - mnew), p1 = __expf(v1 - mnew);
            float p2 = __expf(v2v - mnew), p3 = __expf(v3 - mnew);
            float rs = (p0 + p1) + (p2 + p3);
#pragma unroll
            for (int off = 8; off; off >>= 1)
                rs += __shfl_xor_sync(0xffffffffu, rs, off);
            lrun[i] = lrun[i] * f + rs;
            mrun[i] = mnew;
            u64 ff = pack2(f, f);
#pragma unroll
            for (int g = 0; g < 8; g++) fmul2(o2[i][g], ff);
            *(float4*)&sP[(4 * ty + i) * TSTR + 4 * tx] = make_float4(p0, p1, p2, p3);
        }
        __syncthreads();

        // ---- O += P V ----
#pragma unroll 2
        for (int mm = 0; mm < 64; mm++) {
            u64 pp[4];
#pragma unroll
            for (int i = 0; i < 4; i++) {
                float pv = sP[(4 * ty + i) * TSTR + mm];
                pp[i] = pack2(pv, pv);
            }
            const float* vrow = &sV[mm * 256 + 2 * tx];
            u64 vv[8];
#pragma unroll
            for (int g = 0; g < 8; g++) vv[g] = *(const u64*)&vrow[32 * g];
#pragma unroll
            for (int g = 0; g < 8; g++) {
                ffma2(o2[0][g], pp[0], vv[g]);
                ffma2(o2[1][g], pp[1], vv[g]);
                ffma2(o2[2][g], pp[2], vv[g]);
                ffma2(o2[3][g], pp[3], vv[g]);
            }
        }
    }

    // ---- epilogue: out[b][c][n] = gamma * O[c][n]/l[n] + g[b][c][n] ----
    const float gamma = gamma_p[0];
    const float* gb = gin + (size_t)b * CIN_ * NPT;
    float* ob = out + (size_t)b * CIN_ * NPT;
#pragma unroll
    for (int i = 0; i < 4; i++) {
        float rl = 1.0f / lrun[i];
        int n = n0 + 4 * ty + i;
#pragma unroll
        for (int g = 0; g < 8; g++) {
            float a, bval; unpack2(o2[i][g], a, bval);
            int c0 = 2 * tx + 32 * g;
            size_t i0 = (size_t)c0 * NPT + n;
            ob[i0]        = gamma * (a * rl)    + gb[i0];
            ob[i0 + NPT]  = gamma * (bval * rl) + gb[i0 + NPT];
        }
    }
}

// ---------------- launch ----------------
extern "C" void kernel_launch(void* const* d_in, const int* in_sizes, int n_in,
                              void* d_out, int out_size)
{
    const float* x     = (const float*)d_in[0];
    const float* g     = (const float*)d_in[1];
    const float* Wq    = (const float*)d_in[2];
    const float* bq    = (const float*)d_in[3];
    const float* Wk    = (const float*)d_in[4];
    const float* bk    = (const float*)d_in[5];
    const float* Wv    = (const float*)d_in[6];
    const float* bv    = (const float*)d_in[7];
    const float* gamma = (const float*)d_in[8];
    float* out = (float*)d_out;

    (void)in_sizes; (void)n_in; (void)out_size;

    const int ATTN_SMEM = (2 * 128 * TSTR + 64 * 256 + 64 * TSTR) * (int)sizeof(float);
    cudaFuncSetAttribute(attn_kernel, cudaFuncAttributeMaxDynamicSharedMemorySize, ATTN_SMEM);

    // projections
    proj_kernel<CQK_, 0><<<dim3(NPT / 64, CQK_ / 64, BSZ), 256>>>(Wq, bq, x);
    proj_kernel<CQK_, 1><<<dim3(NPT / 64, CQK_ / 64, BSZ), 256>>>(Wk, bk, g);
    proj_kernel<CIN_, 2><<<dim3(NPT / 64, CIN_ / 64, BSZ), 256>>>(Wv, bv, g);

    // fused attention + epilogue
    attn_kernel<<<dim3(NPT / 64, BSZ), 256, ATTN_SMEM>>>(g, gamma, out);
}